// round 11
// baseline (speedup 1.0000x reference)
#include <cuda_runtime.h>
#include <cuda_bf16.h>

// Problem constants
#define BATCH 4
#define CIN   64
#define HH    128
#define WW    128
#define OUTC  64
#define K2N   9
#define NPOS  (BATCH*HH*WW)

// Scratch (device globals; no allocation allowed)
__device__ __align__(16) float g_xT[BATCH*HH*WW*CIN];   // [b][y][x][c]
__device__ __align__(16) float g_post[NPOS*28];         // partial half0, then final after combine
__device__ __align__(16) float g_post2[NPOS*28];        // partial half1
__device__ __align__(16) float g_cwT[9*64*28];          // [tap][c][j]
__device__ __align__(16) float g_dwT[9*64*64];          // [k][c][o]  (non-duplicated)

// ------------------------- f32x2 helpers (sm_100+) -------------------------
__device__ __forceinline__ void ffma2(unsigned long long& d,
                                      unsigned long long a,
                                      unsigned long long b) {
    asm("fma.rn.f32x2 %0, %1, %2, %0;" : "+l"(d) : "l"(a), "l"(b));
}
__device__ __forceinline__ unsigned long long dup2(float a) {
    unsigned long long r;
    asm("mov.b64 %0, {%1, %1};" : "=l"(r) : "f"(a));
    return r;
}

// ---------------------------------------------------------------------------
// Kernel W: weight transposes (tiny)
// ---------------------------------------------------------------------------
__global__ void kW(const float* __restrict__ ow, const float* __restrict__ mw,
                   const float* __restrict__ dw) {
    int i = blockIdx.x * blockDim.x + threadIdx.x;
    int stride = gridDim.x * blockDim.x;
    for (int idx = i; idx < 9*64*28; idx += stride) {
        int j   = idx % 28;
        int c   = (idx / 28) % 64;
        int tap = idx / (28*64);
        float v = 0.f;
        if (j < 18)      v = ow[j*576 + c*9 + tap];
        else if (j < 27) v = mw[(j-18)*576 + c*9 + tap];
        g_cwT[idx] = v;
    }
    // g_dwT[k][c][o] = dw[o][c][k]
    for (int idx = i; idx < 9*64*64; idx += stride) {
        int o = idx & 63;
        int c = (idx >> 6) & 63;
        int k = idx >> 12;
        g_dwT[idx] = dw[o*576 + c*9 + k];
    }
}

// ---------------------------------------------------------------------------
// Kernel A: NCHW -> NHWC transpose of x  (grid = BATCH*HH, block = 128)
// ---------------------------------------------------------------------------
__global__ __launch_bounds__(128) void kA(const float* __restrict__ x) {
    int by = blockIdx.x;
    int b = by >> 7, y = by & 127;
    int xq = threadIdx.x;
    const float* src = x + ((size_t)(b*CIN)*HH + y) * WW + xq;
    float* dst = g_xT + (((size_t)b*HH + y) * WW + xq) * CIN;
#pragma unroll
    for (int c4 = 0; c4 < 16; ++c4) {
        float4 v;
        v.x = src[(size_t)(c4*4+0)*HH*WW];
        v.y = src[(size_t)(c4*4+1)*HH*WW];
        v.z = src[(size_t)(c4*4+2)*HH*WW];
        v.w = src[(size_t)(c4*4+3)*HH*WW];
        *reinterpret_cast<float4*>(dst + c4*4) = v;
    }
}

// ---------------------------------------------------------------------------
// Kernel B: offset + mask conv partials over a 32-channel half.
// grid = dim3(512, 2). Writes RAW accumulators to g_post / g_post2.
// ---------------------------------------------------------------------------
__global__ __launch_bounds__(128) void kB() {
    __shared__ __align__(16) float sw[32*28];   // weights for one tap, 32 channels
    int by = blockIdx.x;
    int b = by >> 7, y = by & 127;
    int xq = threadIdx.x;
    int c0 = blockIdx.y * 32;
    float* gdst = blockIdx.y ? g_post2 : g_post;

    unsigned long long acc[14];
#pragma unroll
    for (int j = 0; j < 14; ++j) acc[j] = 0ULL;

    for (int tap = 0; tap < 9; ++tap) {
        __syncthreads();
        for (int t = threadIdx.x; t < 32*28/4; t += 128)
            reinterpret_cast<float4*>(sw)[t] =
                reinterpret_cast<const float4*>(g_cwT + tap*64*28 + c0*28)[t];
        __syncthreads();

        int ky = tap / 3, kx = tap % 3;
        int ys = y + ky - 1, xs = xq + kx - 1;
        if (ys < 0 || ys > 127 || xs < 0 || xs > 127) continue;  // zero pad

        const float4* xp = reinterpret_cast<const float4*>(
            g_xT + (((size_t)b*HH + ys) * WW + xs) * CIN + c0);
#pragma unroll 4
        for (int c4 = 0; c4 < 8; ++c4) {
            float4 xv = xp[c4];
#pragma unroll
            for (int cc = 0; cc < 4; ++cc) {
                unsigned long long ad = dup2((&xv.x)[cc]);
                const float4* wp = reinterpret_cast<const float4*>(sw + (c4*4+cc)*28);
#pragma unroll
                for (int j4 = 0; j4 < 7; ++j4) {
                    float4 w = wp[j4];
                    const unsigned long long* wu =
                        reinterpret_cast<const unsigned long long*>(&w);
                    ffma2(acc[j4*2+0], ad, wu[0]);
                    ffma2(acc[j4*2+1], ad, wu[1]);
                }
            }
        }
    }

    float* dst = gdst + (((size_t)(b*HH) + y) * WW + xq) * 28;
#pragma unroll
    for (int j2 = 0; j2 < 14; ++j2)
        *reinterpret_cast<unsigned long long*>(dst + 2*j2) = acc[j2];
}

// ---------------------------------------------------------------------------
// Kernel Bc: combine halves, add bias, sigmoid masks. In-place into g_post.
// ---------------------------------------------------------------------------
__global__ __launch_bounds__(128) void kBc(const float* __restrict__ ob,
                                           const float* __restrict__ mb) {
    size_t pos = (size_t)blockIdx.x * 128 + threadIdx.x;
    float* a = g_post + pos * 28;
    const float* bpart = g_post2 + pos * 28;
    float r[28];
#pragma unroll
    for (int q = 0; q < 7; ++q) {
        float4 va = reinterpret_cast<const float4*>(a)[q];
        float4 vb = reinterpret_cast<const float4*>(bpart)[q];
        r[4*q+0] = va.x + vb.x; r[4*q+1] = va.y + vb.y;
        r[4*q+2] = va.z + vb.z; r[4*q+3] = va.w + vb.w;
    }
#pragma unroll
    for (int j = 0; j < 18; ++j) r[j] += ob[j];
#pragma unroll
    for (int j = 0; j < 9; ++j) {
        float t = r[18+j] + mb[j];
        r[18+j] = 1.f / (1.f + __expf(-t));
    }
    r[27] = 0.f;
#pragma unroll
    for (int q = 0; q < 7; ++q)
        reinterpret_cast<float4*>(a)[q] =
            make_float4(r[4*q+0], r[4*q+1], r[4*q+2], r[4*q+3]);
}

// ---------------------------------------------------------------------------
// Kernel C: bilinear sampling + deform GEMM, FFMA2.
// grid = BATCH*HH, block = 256 (8 warps: 2x latency hiding vs 128).
// Smem: A [64c][128pos] (32KB) + W [64c][64o] (16KB) = 48KB.
// Thread tile: 4 positions (2 strided x-pairs) x 8 outputs.
// Sampling: thread-halves split the channel range (c4 0-7 / 8-15).
// ---------------------------------------------------------------------------
__global__ __launch_bounds__(256, 3) void kC(const float* __restrict__ db,
                                             float* __restrict__ out) {
    __shared__ __align__(16) float A_sh[64][128];
    __shared__ __align__(16) float W_sh[64][64];   // [c][o]

    int by = blockIdx.x;
    int b = by >> 7, y = by & 127;
    int tid   = threadIdx.x;
    int pcol  = tid & 31;     // x pairs at pcol*2 + i2*64, i2 in {0,1}
    int og    = tid >> 5;     // outputs o = og*8 + j  (og 0..7)
    int xq    = tid & 127;    // sampling position
    int chalf = tid >> 7;     // sampling channel half (c4 range)

    // acc[i2*8 + j] : f32x2 pair over two adjacent x, output o = og*8+j
    unsigned long long acc[16];
#pragma unroll
    for (int j = 0; j < 8; ++j) {
        unsigned long long bd = dup2(db[og*8 + j]);
        acc[j]   = bd;
        acc[8+j] = bd;
    }

    const float* pi = g_post + (((size_t)(b*HH) + y) * WW + xq) * 28;

    for (int k = 0; k < 9; ++k) {
        __syncthreads();  // previous GEMM done reading A_sh / W_sh

        // ---- fill W slab for this k: 1024 float4 / 256 threads = 4 each ----
        {
            const float4* src = reinterpret_cast<const float4*>(g_dwT + (size_t)k*4096);
            float4* dst = reinterpret_cast<float4*>(&W_sh[0][0]);
#pragma unroll
            for (int t = 0; t < 4; ++t)
                dst[tid + t*256] = src[tid + t*256];
        }

        // ---- sampling: position xq, channel half chalf ----
        {
            float dy = pi[2*k], dx = pi[2*k+1], m = pi[18+k];
            int ky = k / 3, kx = k % 3;
            float py = dy + (float)(ky + y  - 1);
            float px = dx + (float)(kx + xq - 1);
            float fy = floorf(py), fx = floorf(px);
            float wy1 = py - fy, wx1 = px - fx;
            float wy0 = 1.f - wy1, wx0 = 1.f - wx1;
            int y0 = (int)fy, x0 = (int)fx;
            int y1 = y0 + 1, x1 = x0 + 1;
            bool vy0 = (y0 >= 0) & (y0 < HH), vy1 = (y1 >= 0) & (y1 < HH);
            bool vx0 = (x0 >= 0) & (x0 < WW), vx1 = (x1 >= 0) & (x1 < WW);
            float w00 = (vy0 && vx0) ? wy0*wx0*m : 0.f;
            float w01 = (vy0 && vx1) ? wy0*wx1*m : 0.f;
            float w10 = (vy1 && vx0) ? wy1*wx0*m : 0.f;
            float w11 = (vy1 && vx1) ? wy1*wx1*m : 0.f;
            int yc0 = min(max(y0, 0), HH-1), yc1 = min(max(y1, 0), HH-1);
            int xc0 = min(max(x0, 0), WW-1), xc1 = min(max(x1, 0), WW-1);

            int cbase = chalf * 32;  // channel offset for this half
            const float4* p00 = reinterpret_cast<const float4*>(g_xT + (((size_t)b*HH + yc0)*WW + xc0)*CIN + cbase);
            const float4* p01 = reinterpret_cast<const float4*>(g_xT + (((size_t)b*HH + yc0)*WW + xc1)*CIN + cbase);
            const float4* p10 = reinterpret_cast<const float4*>(g_xT + (((size_t)b*HH + yc1)*WW + xc0)*CIN + cbase);
            const float4* p11 = reinterpret_cast<const float4*>(g_xT + (((size_t)b*HH + yc1)*WW + xc1)*CIN + cbase);

#pragma unroll 4
            for (int c4 = 0; c4 < 8; ++c4) {
                float4 a = p00[c4], bb = p01[c4], cv = p10[c4], d = p11[c4];
                int cr = cbase + c4*4;
                A_sh[cr+0][xq] = w00*a.x + w01*bb.x + w10*cv.x + w11*d.x;
                A_sh[cr+1][xq] = w00*a.y + w01*bb.y + w10*cv.y + w11*d.y;
                A_sh[cr+2][xq] = w00*a.z + w01*bb.z + w10*cv.z + w11*d.z;
                A_sh[cr+3][xq] = w00*a.w + w01*bb.w + w10*cv.w + w11*d.w;
            }
        }

        __syncthreads();  // A + W ready

        // ---- GEMM: 64 c; per c: 4 LDS + 8 MOV + 16 FFMA2 ----
#pragma unroll 2
        for (int c = 0; c < 64; ++c) {
            const float4* wf = reinterpret_cast<const float4*>(&W_sh[c][og*8]);
            float4 wlo = wf[0], whi = wf[1];
            unsigned long long w0 = dup2(wlo.x), w1 = dup2(wlo.y);
            unsigned long long w2 = dup2(wlo.z), w3 = dup2(wlo.w);
            unsigned long long w4 = dup2(whi.x), w5 = dup2(whi.y);
            unsigned long long w6 = dup2(whi.z), w7 = dup2(whi.w);

            const float* ac = &A_sh[c][pcol*2];
            unsigned long long a0 = *reinterpret_cast<const unsigned long long*>(ac);
            unsigned long long a1 = *reinterpret_cast<const unsigned long long*>(ac + 64);

            ffma2(acc[ 0], a0, w0); ffma2(acc[ 1], a0, w1);
            ffma2(acc[ 2], a0, w2); ffma2(acc[ 3], a0, w3);
            ffma2(acc[ 4], a0, w4); ffma2(acc[ 5], a0, w5);
            ffma2(acc[ 6], a0, w6); ffma2(acc[ 7], a0, w7);
            ffma2(acc[ 8], a1, w0); ffma2(acc[ 9], a1, w1);
            ffma2(acc[10], a1, w2); ffma2(acc[11], a1, w3);
            ffma2(acc[12], a1, w4); ffma2(acc[13], a1, w5);
            ffma2(acc[14], a1, w6); ffma2(acc[15], a1, w7);
        }
    }

    // ---- epilogue: packed 8-byte stores, coalesced per warp ----
#pragma unroll
    for (int j = 0; j < 8; ++j) {
        int o = og*8 + j;
        float* orow = out + (((size_t)(b*OUTC) + o)*HH + y) * WW;
        *reinterpret_cast<unsigned long long*>(orow + pcol*2)      = acc[j];
        *reinterpret_cast<unsigned long long*>(orow + pcol*2 + 64) = acc[8+j];
    }
}

// ---------------------------------------------------------------------------
extern "C" void kernel_launch(void* const* d_in, const int* in_sizes, int n_in,
                              void* d_out, int out_size) {
    const float* x   = (const float*)d_in[0];
    const float* ow  = (const float*)d_in[1];
    const float* ob  = (const float*)d_in[2];
    const float* mw  = (const float*)d_in[3];
    const float* mb  = (const float*)d_in[4];
    const float* dw  = (const float*)d_in[5];
    const float* db  = (const float*)d_in[6];
    float* out = (float*)d_out;

    kW<<<64, 256>>>(ow, mw, dw);
    kA<<<BATCH*HH, 128>>>(x);
    kB<<<dim3(BATCH*HH, 2), 128>>>();
    kBc<<<NPOS/128, 128>>>(ob, mb);
    kC<<<BATCH*HH, 256>>>(db, out);
}

// round 12
// speedup vs baseline: 1.3850x; 1.3850x over previous
#include <cuda_runtime.h>
#include <cuda_bf16.h>

// Problem constants
#define BATCH 4
#define CIN   64
#define HH    128
#define WW    128
#define OUTC  64
#define K2N   9
#define NPOS  (BATCH*HH*WW)

// Scratch (device globals; no allocation allowed)
__device__ __align__(16) float g_xT[BATCH*HH*WW*CIN];   // [b][y][x][c]
__device__ __align__(16) float g_post[NPOS*28];         // kB partial half0 (raw)
__device__ __align__(16) float g_post2[NPOS*28];        // kB partial half1 (raw)
__device__ __align__(16) float g_postT[28*NPOS];        // [j][pos] final offsets/masks (transposed)
__device__ __align__(16) float g_cwT[9*64*28];          // [tap][c][j]
__device__ __align__(16) float g_dwT[9*64*64];          // [k][c][o]

// ------------------------- f32x2 helpers (sm_100+) -------------------------
__device__ __forceinline__ void ffma2(unsigned long long& d,
                                      unsigned long long a,
                                      unsigned long long b) {
    asm("fma.rn.f32x2 %0, %1, %2, %0;" : "+l"(d) : "l"(a), "l"(b));
}
__device__ __forceinline__ unsigned long long dup2(float a) {
    unsigned long long r;
    asm("mov.b64 %0, {%1, %1};" : "=l"(r) : "f"(a));
    return r;
}

// ---------------------------------------------------------------------------
// Kernel W: weight transposes (tiny)
// ---------------------------------------------------------------------------
__global__ void kW(const float* __restrict__ ow, const float* __restrict__ mw,
                   const float* __restrict__ dw) {
    int i = blockIdx.x * blockDim.x + threadIdx.x;
    int stride = gridDim.x * blockDim.x;
    for (int idx = i; idx < 9*64*28; idx += stride) {
        int j   = idx % 28;
        int c   = (idx / 28) % 64;
        int tap = idx / (28*64);
        float v = 0.f;
        if (j < 18)      v = ow[j*576 + c*9 + tap];
        else if (j < 27) v = mw[(j-18)*576 + c*9 + tap];
        g_cwT[idx] = v;
    }
    // g_dwT[k][c][o] = dw[o][c][k]
    for (int idx = i; idx < 9*64*64; idx += stride) {
        int o = idx & 63;
        int c = (idx >> 6) & 63;
        int k = idx >> 12;
        g_dwT[idx] = dw[o*576 + c*9 + k];
    }
}

// ---------------------------------------------------------------------------
// Kernel A: NCHW -> NHWC transpose of x  (grid = BATCH*HH, block = 128)
// ---------------------------------------------------------------------------
__global__ __launch_bounds__(128) void kA(const float* __restrict__ x) {
    int by = blockIdx.x;
    int b = by >> 7, y = by & 127;
    int xq = threadIdx.x;
    const float* src = x + ((size_t)(b*CIN)*HH + y) * WW + xq;
    float* dst = g_xT + (((size_t)b*HH + y) * WW + xq) * CIN;
#pragma unroll
    for (int c4 = 0; c4 < 16; ++c4) {
        float4 v;
        v.x = src[(size_t)(c4*4+0)*HH*WW];
        v.y = src[(size_t)(c4*4+1)*HH*WW];
        v.z = src[(size_t)(c4*4+2)*HH*WW];
        v.w = src[(size_t)(c4*4+3)*HH*WW];
        *reinterpret_cast<float4*>(dst + c4*4) = v;
    }
}

// ---------------------------------------------------------------------------
// Kernel B: offset + mask conv partials over a 32-channel half.
// grid = dim3(512, 2). Reads x directly in NCHW (coalesced LDG.32 per c).
// ---------------------------------------------------------------------------
__global__ __launch_bounds__(128) void kB(const float* __restrict__ x) {
    __shared__ __align__(16) float sw[32*28];   // weights for one tap, 32 channels
    int by = blockIdx.x;
    int b = by >> 7, y = by & 127;
    int xq = threadIdx.x;
    int c0 = blockIdx.y * 32;
    float* gdst = blockIdx.y ? g_post2 : g_post;

    unsigned long long acc[14];
#pragma unroll
    for (int j = 0; j < 14; ++j) acc[j] = 0ULL;

    for (int tap = 0; tap < 9; ++tap) {
        __syncthreads();
        for (int t = threadIdx.x; t < 32*28/4; t += 128)
            reinterpret_cast<float4*>(sw)[t] =
                reinterpret_cast<const float4*>(g_cwT + tap*64*28 + c0*28)[t];
        __syncthreads();

        int ky = tap / 3, kx = tap % 3;
        int ys = y + ky - 1, xs = xq + kx - 1;
        if (ys < 0 || ys > 127 || xs < 0 || xs > 127) continue;  // zero pad

        const float* xc = x + ((size_t)(b*CIN + c0)*HH + ys) * WW + xs;
#pragma unroll 4
        for (int c = 0; c < 32; ++c) {
            unsigned long long ad = dup2(xc[(size_t)c*HH*WW]);
            const float4* wp = reinterpret_cast<const float4*>(sw + c*28);
#pragma unroll
            for (int j4 = 0; j4 < 7; ++j4) {
                float4 w = wp[j4];
                const unsigned long long* wu =
                    reinterpret_cast<const unsigned long long*>(&w);
                ffma2(acc[j4*2+0], ad, wu[0]);
                ffma2(acc[j4*2+1], ad, wu[1]);
            }
        }
    }

    float* dst = gdst + (((size_t)(b*HH) + y) * WW + xq) * 28;
#pragma unroll
    for (int j2 = 0; j2 < 14; ++j2)
        *reinterpret_cast<unsigned long long*>(dst + 2*j2) = acc[j2];
}

// ---------------------------------------------------------------------------
// Kernel Bc: combine halves, add bias, sigmoid masks -> TRANSPOSED g_postT.
// ---------------------------------------------------------------------------
__global__ __launch_bounds__(128) void kBc(const float* __restrict__ ob,
                                           const float* __restrict__ mb) {
    size_t pos = (size_t)blockIdx.x * 128 + threadIdx.x;
    const float* a = g_post + pos * 28;
    const float* bpart = g_post2 + pos * 28;
    float r[28];
#pragma unroll
    for (int q = 0; q < 7; ++q) {
        float4 va = reinterpret_cast<const float4*>(a)[q];
        float4 vb = reinterpret_cast<const float4*>(bpart)[q];
        r[4*q+0] = va.x + vb.x; r[4*q+1] = va.y + vb.y;
        r[4*q+2] = va.z + vb.z; r[4*q+3] = va.w + vb.w;
    }
#pragma unroll
    for (int j = 0; j < 18; ++j) r[j] += ob[j];
#pragma unroll
    for (int j = 0; j < 9; ++j) {
        float t = r[18+j] + mb[j];
        r[18+j] = 1.f / (1.f + __expf(-t));
    }
#pragma unroll
    for (int j = 0; j < 27; ++j)
        g_postT[(size_t)j*NPOS + pos] = r[j];
}

// ---------------------------------------------------------------------------
// Kernel C: bilinear sampling + deform GEMM, FFMA2.
// grid = BATCH*HH, block = 128.  Smem: A [64][128] + W [64][64] = 48KB.
// Sampling: each warp covers its own 32 positions, 2 per iteration;
//   lane = (sub, c4): 16 lanes jointly load one position's 256B corner
//   vectors (coalesced, 4 wf per LDG.128 instead of 32).
// A_sh XOR swizzle: element A[c][pos] stored at col pos ^ ((c>>2)<<1)
//   -> conflict-free STS; GEMM pair reads stay contiguous & 8B aligned.
// GEMM: identical to the 324us R8 kernel (8 pos x 8 o per thread).
// ---------------------------------------------------------------------------
__global__ __launch_bounds__(128) void kC(const float* __restrict__ db,
                                          float* __restrict__ out) {
    __shared__ __align__(16) float A_sh[64][128];
    __shared__ __align__(16) float W_sh[64][64];   // [c][o]

    int by = blockIdx.x;
    int b = by >> 7, y = by & 127;
    int tid  = threadIdx.x;
    int lane = tid & 31;
    int warp = tid >> 5;
    int pcol = tid & 15;     // GEMM: x pairs at pcol*2 + i2*32
    int og   = tid >> 4;     // GEMM: outputs o = og*8 + j
    int sub  = lane >> 4;    // sampling: position sub-slot (0/1)
    int c4   = lane & 15;    // sampling: channel quad

    unsigned long long acc[32];
#pragma unroll
    for (int j = 0; j < 8; ++j) {
        unsigned long long bd = dup2(db[og*8 + j]);
#pragma unroll
        for (int i2 = 0; i2 < 4; ++i2) acc[i2*8+j] = bd;
    }

    size_t rowbase = ((size_t)(b*HH) + y) * WW;   // position index base

    for (int k = 0; k < 9; ++k) {
        __syncthreads();  // previous GEMM done reading A_sh / W_sh

        // ---- fill W slab for this k: 1024 float4, 8 per thread ----
        {
            const float4* src = reinterpret_cast<const float4*>(g_dwT + (size_t)k*4096);
            float4* dst = reinterpret_cast<float4*>(&W_sh[0][0]);
#pragma unroll
            for (int t = 0; t < 8; ++t)
                dst[tid + t*128] = src[tid + t*128];
        }

        // ---- per-thread offset scalars for position tid (coalesced) ----
        float my_dy = g_postT[(size_t)(2*k  )*NPOS + rowbase + tid];
        float my_dx = g_postT[(size_t)(2*k+1)*NPOS + rowbase + tid];
        float my_m  = g_postT[(size_t)(18+k )*NPOS + rowbase + tid];
        int ky = k / 3, kx = k % 3;

        // ---- sampling: warp covers positions warp*32 .. warp*32+31 ----
#pragma unroll 4
        for (int i = 0; i < 16; ++i) {
            int pl  = 2*i + sub;          // lane (within warp) owning this pos
            int pos = warp*32 + pl;
            float dy = __shfl_sync(0xffffffffu, my_dy, pl);
            float dx = __shfl_sync(0xffffffffu, my_dx, pl);
            float m  = __shfl_sync(0xffffffffu, my_m,  pl);

            float py = dy + (float)(ky + y   - 1);
            float px = dx + (float)(kx + pos - 1);
            float fy = floorf(py), fx = floorf(px);
            float wy1 = py - fy, wx1 = px - fx;
            float wy0 = 1.f - wy1, wx0 = 1.f - wx1;
            int y0 = (int)fy, x0 = (int)fx;
            int y1 = y0 + 1, x1 = x0 + 1;
            bool vy0 = (y0 >= 0) & (y0 < HH), vy1 = (y1 >= 0) & (y1 < HH);
            bool vx0 = (x0 >= 0) & (x0 < WW), vx1 = (x1 >= 0) & (x1 < WW);
            float w00 = (vy0 && vx0) ? wy0*wx0*m : 0.f;
            float w01 = (vy0 && vx1) ? wy0*wx1*m : 0.f;
            float w10 = (vy1 && vx0) ? wy1*wx0*m : 0.f;
            float w11 = (vy1 && vx1) ? wy1*wx1*m : 0.f;
            int yc0 = min(max(y0, 0), HH-1), yc1 = min(max(y1, 0), HH-1);
            int xc0 = min(max(x0, 0), WW-1), xc1 = min(max(x1, 0), WW-1);

            const float4* p00 = reinterpret_cast<const float4*>(g_xT + (((size_t)b*HH + yc0)*WW + xc0)*CIN);
            const float4* p01 = reinterpret_cast<const float4*>(g_xT + (((size_t)b*HH + yc0)*WW + xc1)*CIN);
            const float4* p10 = reinterpret_cast<const float4*>(g_xT + (((size_t)b*HH + yc1)*WW + xc0)*CIN);
            const float4* p11 = reinterpret_cast<const float4*>(g_xT + (((size_t)b*HH + yc1)*WW + xc1)*CIN);

            float4 a = p00[c4], bb = p01[c4], cv = p10[c4], d = p11[c4];
            float v0 = w00*a.x + w01*bb.x + w10*cv.x + w11*d.x;
            float v1 = w00*a.y + w01*bb.y + w10*cv.y + w11*d.y;
            float v2 = w00*a.z + w01*bb.z + w10*cv.z + w11*d.z;
            float v3 = w00*a.w + w01*bb.w + w10*cv.w + w11*d.w;

            int col = pos ^ (c4 << 1);    // XOR swizzle (bank-conflict-free)
            A_sh[c4*4+0][col] = v0;
            A_sh[c4*4+1][col] = v1;
            A_sh[c4*4+2][col] = v2;
            A_sh[c4*4+3][col] = v3;
        }

        __syncthreads();  // A + W ready

        // ---- GEMM: 64 c; per c: 6 LDS + 8 MOV + 32 FFMA2 ----
#pragma unroll 2
        for (int c = 0; c < 64; ++c) {
            const float4* wf = reinterpret_cast<const float4*>(&W_sh[c][og*8]);
            float4 wlo = wf[0], whi = wf[1];
            unsigned long long w0 = dup2(wlo.x), w1 = dup2(wlo.y);
            unsigned long long w2 = dup2(wlo.z), w3 = dup2(wlo.w);
            unsigned long long w4 = dup2(whi.x), w5 = dup2(whi.y);
            unsigned long long w6 = dup2(whi.z), w7 = dup2(whi.w);

            int cx = (pcol*2) ^ ((c >> 2) << 1);   // swizzled pair column
            const float* ar = &A_sh[c][0];
            unsigned long long a0 = *reinterpret_cast<const unsigned long long*>(ar + cx);
            unsigned long long a1 = *reinterpret_cast<const unsigned long long*>(ar + cx + 32);
            unsigned long long a2 = *reinterpret_cast<const unsigned long long*>(ar + cx + 64);
            unsigned long long a3 = *reinterpret_cast<const unsigned long long*>(ar + cx + 96);

            ffma2(acc[ 0], a0, w0); ffma2(acc[ 1], a0, w1);
            ffma2(acc[ 2], a0, w2); ffma2(acc[ 3], a0, w3);
            ffma2(acc[ 4], a0, w4); ffma2(acc[ 5], a0, w5);
            ffma2(acc[ 6], a0, w6); ffma2(acc[ 7], a0, w7);
            ffma2(acc[ 8], a1, w0); ffma2(acc[ 9], a1, w1);
            ffma2(acc[10], a1, w2); ffma2(acc[11], a1, w3);
            ffma2(acc[12], a1, w4); ffma2(acc[13], a1, w5);
            ffma2(acc[14], a1, w6); ffma2(acc[15], a1, w7);
            ffma2(acc[16], a2, w0); ffma2(acc[17], a2, w1);
            ffma2(acc[18], a2, w2); ffma2(acc[19], a2, w3);
            ffma2(acc[20], a2, w4); ffma2(acc[21], a2, w5);
            ffma2(acc[22], a2, w6); ffma2(acc[23], a2, w7);
            ffma2(acc[24], a3, w0); ffma2(acc[25], a3, w1);
            ffma2(acc[26], a3, w2); ffma2(acc[27], a3, w3);
            ffma2(acc[28], a3, w4); ffma2(acc[29], a3, w5);
            ffma2(acc[30], a3, w6); ffma2(acc[31], a3, w7);
        }
    }

    // ---- epilogue: packed 8-byte stores, coalesced per half-warp ----
#pragma unroll
    for (int j = 0; j < 8; ++j) {
        int o = og*8 + j;
        float* orow = out + (((size_t)(b*OUTC) + o)*HH + y) * WW;
#pragma unroll
        for (int i2 = 0; i2 < 4; ++i2)
            *reinterpret_cast<unsigned long long*>(orow + pcol*2 + i2*32) =
                acc[i2*8+j];
    }
}

// ---------------------------------------------------------------------------
extern "C" void kernel_launch(void* const* d_in, const int* in_sizes, int n_in,
                              void* d_out, int out_size) {
    const float* x   = (const float*)d_in[0];
    const float* ow  = (const float*)d_in[1];
    const float* ob  = (const float*)d_in[2];
    const float* mw  = (const float*)d_in[3];
    const float* mb  = (const float*)d_in[4];
    const float* dw  = (const float*)d_in[5];
    const float* db  = (const float*)d_in[6];
    float* out = (float*)d_out;

    kW<<<64, 256>>>(ow, mw, dw);
    kA<<<BATCH*HH, 128>>>(x);
    kB<<<dim3(BATCH*HH, 2), 128>>>(x);
    kBc<<<NPOS/128, 128>>>(ob, mb);
    kC<<<BATCH*HH, 128>>>(db, out);
}

// round 13
// speedup vs baseline: 1.4307x; 1.0330x over previous
#include <cuda_runtime.h>
#include <cuda_bf16.h>

// Problem constants
#define BATCH 4
#define CIN   64
#define HH    128
#define WW    128
#define OUTC  64
#define K2N   9
#define NPOS  (BATCH*HH*WW)

// Scratch (device globals; no allocation allowed)
__device__ __align__(16) float g_xT[BATCH*HH*WW*CIN];   // [b][y][x][c]
__device__ __align__(16) float g_postT[28*NPOS];        // [j][pos] offsets/masks (transposed)
__device__ __align__(16) float g_cwT[9*64*28];          // [tap][c][j]
__device__ __align__(16) float g_dwT[9*64*64];          // [k][c][o]

// ------------------------- f32x2 helpers (sm_100+) -------------------------
__device__ __forceinline__ void ffma2(unsigned long long& d,
                                      unsigned long long a,
                                      unsigned long long b) {
    asm("fma.rn.f32x2 %0, %1, %2, %0;" : "+l"(d) : "l"(a), "l"(b));
}
__device__ __forceinline__ unsigned long long dup2(float a) {
    unsigned long long r;
    asm("mov.b64 %0, {%1, %1};" : "=l"(r) : "f"(a));
    return r;
}

// ---------------------------------------------------------------------------
// Kernel W: weight transposes (tiny)
// ---------------------------------------------------------------------------
__global__ void kW(const float* __restrict__ ow, const float* __restrict__ mw,
                   const float* __restrict__ dw) {
    int i = blockIdx.x * blockDim.x + threadIdx.x;
    int stride = gridDim.x * blockDim.x;
    for (int idx = i; idx < 9*64*28; idx += stride) {
        int j   = idx % 28;
        int c   = (idx / 28) % 64;
        int tap = idx / (28*64);
        float v = 0.f;
        if (j < 18)      v = ow[j*576 + c*9 + tap];
        else if (j < 27) v = mw[(j-18)*576 + c*9 + tap];
        g_cwT[idx] = v;
    }
    // g_dwT[k][c][o] = dw[o][c][k]
    for (int idx = i; idx < 9*64*64; idx += stride) {
        int o = idx & 63;
        int c = (idx >> 6) & 63;
        int k = idx >> 12;
        g_dwT[idx] = dw[o*576 + c*9 + k];
    }
}

// ---------------------------------------------------------------------------
// Kernel A: NCHW -> NHWC transpose of x  (grid = BATCH*HH, block = 128)
// ---------------------------------------------------------------------------
__global__ __launch_bounds__(128) void kA(const float* __restrict__ x) {
    int by = blockIdx.x;
    int b = by >> 7, y = by & 127;
    int xq = threadIdx.x;
    const float* src = x + ((size_t)(b*CIN)*HH + y) * WW + xq;
    float* dst = g_xT + (((size_t)b*HH + y) * WW + xq) * CIN;
#pragma unroll
    for (int c4 = 0; c4 < 16; ++c4) {
        float4 v;
        v.x = src[(size_t)(c4*4+0)*HH*WW];
        v.y = src[(size_t)(c4*4+1)*HH*WW];
        v.z = src[(size_t)(c4*4+2)*HH*WW];
        v.w = src[(size_t)(c4*4+3)*HH*WW];
        *reinterpret_cast<float4*>(dst + c4*4) = v;
    }
}

// ---------------------------------------------------------------------------
// Kernel F: FUSED offset/mask conv + bilinear sampling + deform GEMM.
// grid = BATCH*HH (one (b,y) row per block), block = 128.
// Smem: A_sh [64][128] (32KB) + W_sh [64][64] (16KB) = 48KB.
//   Phase 1 reuses W_sh as scratch for the per-tap offset/mask weights.
// Phase 1: thread = position; offset+mask 3x3 conv (all 64 ch), bias+sigmoid,
//   write 27 scalars to g_postT (own-block writes; __syncthreads makes them
//   visible block-wide).
// Phase 2: identical to the R11 kC (coalesced 16-lane sampling, XOR-swizzled
//   A_sh, FFMA2 GEMM, 8 pos x 8 o per thread).
// ---------------------------------------------------------------------------
__global__ __launch_bounds__(128) void kF(const float* __restrict__ x,
                                          const float* __restrict__ ob,
                                          const float* __restrict__ mb,
                                          const float* __restrict__ db,
                                          float* __restrict__ out) {
    __shared__ __align__(16) float A_sh[64][128];
    __shared__ __align__(16) float W_sh[64][64];   // phase2: [c][o]; phase1: cw scratch

    int by = blockIdx.x;
    int b = by >> 7, y = by & 127;
    int tid  = threadIdx.x;
    int lane = tid & 31;
    int warp = tid >> 5;
    size_t rowbase = ((size_t)(b*HH) + y) * WW;   // position index base
    size_t pos = rowbase + tid;

    // ================= Phase 1: offset + mask conv =================
    {
        float* sw = &W_sh[0][0];   // 1792 floats used of 4096
        unsigned long long bacc[14];
#pragma unroll
        for (int j = 0; j < 14; ++j) bacc[j] = 0ULL;

        for (int tap = 0; tap < 9; ++tap) {
            __syncthreads();
            for (int t = tid; t < 448; t += 128)
                reinterpret_cast<float4*>(sw)[t] =
                    reinterpret_cast<const float4*>(g_cwT + tap*1792)[t];
            __syncthreads();

            int ky = tap / 3, kx = tap % 3;
            int ys = y + ky - 1, xs = tid + kx - 1;
            if (ys < 0 || ys > 127 || xs < 0 || xs > 127) continue;  // zero pad

            const float* xc = x + ((size_t)(b*CIN)*HH + ys) * WW + xs;
#pragma unroll 4
            for (int c = 0; c < 64; ++c) {
                unsigned long long ad = dup2(xc[(size_t)c*HH*WW]);
                const float4* wp = reinterpret_cast<const float4*>(sw + c*28);
#pragma unroll
                for (int j4 = 0; j4 < 7; ++j4) {
                    float4 w = wp[j4];
                    const unsigned long long* wu =
                        reinterpret_cast<const unsigned long long*>(&w);
                    ffma2(bacc[j4*2+0], ad, wu[0]);
                    ffma2(bacc[j4*2+1], ad, wu[1]);
                }
            }
        }

        float r[28];
#pragma unroll
        for (int j2 = 0; j2 < 14; ++j2) {
            float2 f = *reinterpret_cast<float2*>(&bacc[j2]);
            r[2*j2+0] = f.x;
            r[2*j2+1] = f.y;
        }
#pragma unroll
        for (int j = 0; j < 18; ++j) r[j] += ob[j];
#pragma unroll
        for (int j = 0; j < 9; ++j) {
            float t = r[18+j] + mb[j];
            r[18+j] = 1.f / (1.f + __expf(-t));
        }
#pragma unroll
        for (int j = 0; j < 27; ++j)
            g_postT[(size_t)j*NPOS + pos] = r[j];
        // visibility of these global writes to the whole block is guaranteed
        // by the __syncthreads() at the top of the phase-2 k-loop.
    }

    // ================= Phase 2: sampling + deform GEMM =================
    int pcol = tid & 15;     // GEMM: x pairs at pcol*2 + i2*32
    int og   = tid >> 4;     // GEMM: outputs o = og*8 + j
    int sub  = lane >> 4;    // sampling: position sub-slot (0/1)
    int c4   = lane & 15;    // sampling: channel quad

    unsigned long long acc[32];
#pragma unroll
    for (int j = 0; j < 8; ++j) {
        unsigned long long bd = dup2(db[og*8 + j]);
#pragma unroll
        for (int i2 = 0; i2 < 4; ++i2) acc[i2*8+j] = bd;
    }

    for (int k = 0; k < 9; ++k) {
        __syncthreads();  // prev GEMM done reading A/W; phase-1 postT visible

        // ---- fill W slab for this k: 1024 float4, 8 per thread ----
        {
            const float4* src = reinterpret_cast<const float4*>(g_dwT + (size_t)k*4096);
            float4* dst = reinterpret_cast<float4*>(&W_sh[0][0]);
#pragma unroll
            for (int t = 0; t < 8; ++t)
                dst[tid + t*128] = src[tid + t*128];
        }

        // ---- per-thread offset scalars for position tid (L1-hot) ----
        float my_dy = g_postT[(size_t)(2*k  )*NPOS + pos];
        float my_dx = g_postT[(size_t)(2*k+1)*NPOS + pos];
        float my_m  = g_postT[(size_t)(18+k )*NPOS + pos];
        int ky = k / 3, kx = k % 3;

        // ---- sampling: warp covers positions warp*32 .. warp*32+31 ----
#pragma unroll 4
        for (int i = 0; i < 16; ++i) {
            int pl  = 2*i + sub;          // lane owning this position
            int spos = warp*32 + pl;
            float dy = __shfl_sync(0xffffffffu, my_dy, pl);
            float dx = __shfl_sync(0xffffffffu, my_dx, pl);
            float m  = __shfl_sync(0xffffffffu, my_m,  pl);

            float py = dy + (float)(ky + y    - 1);
            float px = dx + (float)(kx + spos - 1);
            float fy = floorf(py), fx = floorf(px);
            float wy1 = py - fy, wx1 = px - fx;
            float wy0 = 1.f - wy1, wx0 = 1.f - wx1;
            int y0 = (int)fy, x0 = (int)fx;
            int y1 = y0 + 1, x1 = x0 + 1;
            bool vy0 = (y0 >= 0) & (y0 < HH), vy1 = (y1 >= 0) & (y1 < HH);
            bool vx0 = (x0 >= 0) & (x0 < WW), vx1 = (x1 >= 0) & (x1 < WW);
            float w00 = (vy0 && vx0) ? wy0*wx0*m : 0.f;
            float w01 = (vy0 && vx1) ? wy0*wx1*m : 0.f;
            float w10 = (vy1 && vx0) ? wy1*wx0*m : 0.f;
            float w11 = (vy1 && vx1) ? wy1*wx1*m : 0.f;
            int yc0 = min(max(y0, 0), HH-1), yc1 = min(max(y1, 0), HH-1);
            int xc0 = min(max(x0, 0), WW-1), xc1 = min(max(x1, 0), WW-1);

            const float4* p00 = reinterpret_cast<const float4*>(g_xT + (((size_t)b*HH + yc0)*WW + xc0)*CIN);
            const float4* p01 = reinterpret_cast<const float4*>(g_xT + (((size_t)b*HH + yc0)*WW + xc1)*CIN);
            const float4* p10 = reinterpret_cast<const float4*>(g_xT + (((size_t)b*HH + yc1)*WW + xc0)*CIN);
            const float4* p11 = reinterpret_cast<const float4*>(g_xT + (((size_t)b*HH + yc1)*WW + xc1)*CIN);

            float4 a = p00[c4], bb = p01[c4], cv = p10[c4], d = p11[c4];
            float v0 = w00*a.x + w01*bb.x + w10*cv.x + w11*d.x;
            float v1 = w00*a.y + w01*bb.y + w10*cv.y + w11*d.y;
            float v2 = w00*a.z + w01*bb.z + w10*cv.z + w11*d.z;
            float v3 = w00*a.w + w01*bb.w + w10*cv.w + w11*d.w;

            int col = spos ^ (c4 << 1);   // XOR swizzle (bank-conflict-free)
            A_sh[c4*4+0][col] = v0;
            A_sh[c4*4+1][col] = v1;
            A_sh[c4*4+2][col] = v2;
            A_sh[c4*4+3][col] = v3;
        }

        __syncthreads();  // A + W ready

        // ---- GEMM: 64 c; per c: 6 LDS + 8 MOV + 32 FFMA2 ----
#pragma unroll 2
        for (int c = 0; c < 64; ++c) {
            const float4* wf = reinterpret_cast<const float4*>(&W_sh[c][og*8]);
            float4 wlo = wf[0], whi = wf[1];
            unsigned long long w0 = dup2(wlo.x), w1 = dup2(wlo.y);
            unsigned long long w2 = dup2(wlo.z), w3 = dup2(wlo.w);
            unsigned long long w4 = dup2(whi.x), w5 = dup2(whi.y);
            unsigned long long w6 = dup2(whi.z), w7 = dup2(whi.w);

            int cx = (pcol*2) ^ ((c >> 2) << 1);   // swizzled pair column
            const float* ar = &A_sh[c][0];
            unsigned long long a0 = *reinterpret_cast<const unsigned long long*>(ar + cx);
            unsigned long long a1 = *reinterpret_cast<const unsigned long long*>(ar + cx + 32);
            unsigned long long a2 = *reinterpret_cast<const unsigned long long*>(ar + cx + 64);
            unsigned long long a3 = *reinterpret_cast<const unsigned long long*>(ar + cx + 96);

            ffma2(acc[ 0], a0, w0); ffma2(acc[ 1], a0, w1);
            ffma2(acc[ 2], a0, w2); ffma2(acc[ 3], a0, w3);
            ffma2(acc[ 4], a0, w4); ffma2(acc[ 5], a0, w5);
            ffma2(acc[ 6], a0, w6); ffma2(acc[ 7], a0, w7);
            ffma2(acc[ 8], a1, w0); ffma2(acc[ 9], a1, w1);
            ffma2(acc[10], a1, w2); ffma2(acc[11], a1, w3);
            ffma2(acc[12], a1, w4); ffma2(acc[13], a1, w5);
            ffma2(acc[14], a1, w6); ffma2(acc[15], a1, w7);
            ffma2(acc[16], a2, w0); ffma2(acc[17], a2, w1);
            ffma2(acc[18], a2, w2); ffma2(acc[19], a2, w3);
            ffma2(acc[20], a2, w4); ffma2(acc[21], a2, w5);
            ffma2(acc[22], a2, w6); ffma2(acc[23], a2, w7);
            ffma2(acc[24], a3, w0); ffma2(acc[25], a3, w1);
            ffma2(acc[26], a3, w2); ffma2(acc[27], a3, w3);
            ffma2(acc[28], a3, w4); ffma2(acc[29], a3, w5);
            ffma2(acc[30], a3, w6); ffma2(acc[31], a3, w7);
        }
    }

    // ---- epilogue: packed 8-byte stores, coalesced per half-warp ----
#pragma unroll
    for (int j = 0; j < 8; ++j) {
        int o = og*8 + j;
        float* orow = out + (((size_t)(b*OUTC) + o)*HH + y) * WW;
#pragma unroll
        for (int i2 = 0; i2 < 4; ++i2)
            *reinterpret_cast<unsigned long long*>(orow + pcol*2 + i2*32) =
                acc[i2*8+j];
    }
}

// ---------------------------------------------------------------------------
extern "C" void kernel_launch(void* const* d_in, const int* in_sizes, int n_in,
                              void* d_out, int out_size) {
    const float* x   = (const float*)d_in[0];
    const float* ow  = (const float*)d_in[1];
    const float* ob  = (const float*)d_in[2];
    const float* mw  = (const float*)d_in[3];
    const float* mb  = (const float*)d_in[4];
    const float* dw  = (const float*)d_in[5];
    const float* db  = (const float*)d_in[6];
    float* out = (float*)d_out;

    kW<<<64, 256>>>(ow, mw, dw);
    kA<<<BATCH*HH, 128>>>(x);
    kF<<<BATCH*HH, 128>>>(x, ob, mb, db, out);
}